// round 13
// baseline (speedup 1.0000x reference)
#include <cuda_runtime.h>
#include <cuda_bf16.h>
#include <cuda_fp16.h>
#include <math.h>
#include <cstdint>

#define BATCH   2
#define TSEQ    2048
#define CDIM    1024
#define NHEAD   16
#define HDIM    64

typedef __half fp16;

// ---------------------------------------------------------------------------
// Scratch (__device__ globals; no allocation allowed)
// ---------------------------------------------------------------------------
#define QKV_ELEMS (BATCH * NHEAD * TSEQ * HDIM)
__device__ __align__(128) fp16 g_x16[4096 * 1024];    // x single fp16
__device__ __align__(128) fp16 g_wq[1024 * 3072];     // natural [K][N]
__device__ __align__(128) fp16 g_wp[1024 * 1024];     // natural [K][N]
__device__ __align__(128) fp16 g_q16[QKV_ELEMS];      // q scaled, single fp16
__device__ __align__(128) fp16 g_k16[QKV_ELEMS];      // k single fp16
__device__ __align__(128) fp16 g_v16[QKV_ELEMS];      // v single fp16
__device__ __align__(128) fp16 g_at[4096 * 1024];     // attention out, single

// ---------------------------------------------------------------------------
// Helpers
// ---------------------------------------------------------------------------
__device__ __forceinline__ uint32_t smem_u32(const void* p) {
    uint32_t a;
    asm("{ .reg .u64 t; cvta.to.shared.u64 t, %1; cvt.u32.u64 %0, t; }" : "=r"(a) : "l"(p));
    return a;
}

__device__ __forceinline__ void cp16(uint32_t dst, const void* src) {
    asm volatile("cp.async.cg.shared.global [%0], [%1], 16;" :: "r"(dst), "l"(src));
}
#define CP_COMMIT() asm volatile("cp.async.commit_group;" ::: "memory")
template <int N>
__device__ __forceinline__ void cp_wait() {
    asm volatile("cp.async.wait_group %0;" :: "n"(N) : "memory");
}

__device__ __forceinline__ void ldsm_x4(uint32_t* r, uint32_t addr) {
    asm volatile("ldmatrix.sync.aligned.m8n8.x4.shared.b16 {%0,%1,%2,%3}, [%4];"
                 : "=r"(r[0]), "=r"(r[1]), "=r"(r[2]), "=r"(r[3]) : "r"(addr));
}
__device__ __forceinline__ void ldsm_x4_t(uint32_t* r, uint32_t addr) {
    asm volatile("ldmatrix.sync.aligned.m8n8.x4.trans.shared.b16 {%0,%1,%2,%3}, [%4];"
                 : "=r"(r[0]), "=r"(r[1]), "=r"(r[2]), "=r"(r[3]) : "r"(addr));
}

// D += A * B, m16n8k16 fp16 -> f32
__device__ __forceinline__ void mma_fp16(float* c, const uint32_t* a,
                                         uint32_t b0, uint32_t b1) {
    asm volatile(
        "mma.sync.aligned.m16n8k16.row.col.f32.f16.f16.f32 "
        "{%0,%1,%2,%3}, {%4,%5,%6,%7}, {%8,%9}, {%0,%1,%2,%3};"
        : "+f"(c[0]), "+f"(c[1]), "+f"(c[2]), "+f"(c[3])
        : "r"(a[0]), "r"(a[1]), "r"(a[2]), "r"(a[3]), "r"(b0), "r"(b1));
}

// fp16 pack helpers
__device__ __forceinline__ uint32_t pkh(float a, float b) {
    __half2 h = __floats2half2_rn(a, b);
    return *reinterpret_cast<uint32_t*>(&h);
}

__device__ __forceinline__ float ex2(float x) {
    float y;
    asm("ex2.approx.ftz.f32 %0, %1;" : "=f"(y) : "f"(x));
    return y;
}
// packed fp16 exp2 (one MUFU for two elements)
__device__ __forceinline__ uint32_t ex2h2(uint32_t x) {
    uint32_t y;
    asm("ex2.approx.f16x2 %0, %1;" : "=r"(y) : "r"(x));
    return y;
}

#define ONES_H2 0x3C003C00u   // fp16 {1.0, 1.0}

// swizzle for 128B rows
#define SWZ128(off) ((uint32_t)(off) ^ ((((uint32_t)(off)) >> 3) & 0x70))

// ---------------------------------------------------------------------------
// Merged conversion kernel: three f32 -> fp16 conversions in one launch.
// Segments: x (4M elems), w_qkv (3M), w_proj (1M) -> 2M threads total.
// ---------------------------------------------------------------------------
__global__ __launch_bounds__(256)
void convert_all_kernel(const float* __restrict__ x, fp16* __restrict__ x16,
                        const float* __restrict__ wq, fp16* __restrict__ wq16,
                        const float* __restrict__ wp, fp16* __restrict__ wp16) {
    const int t = blockIdx.x * 256 + threadIdx.x;   // 0 .. 2M-1
    const float* src;
    fp16* dst;
    int i;
    if (t < 1048576)              { src = x;  dst = x16;  i = t * 4; }
    else if (t < 1048576 + 786432) { src = wq; dst = wq16; i = (t - 1048576) * 4; }
    else                           { src = wp; dst = wp16; i = (t - 1835008) * 4; }
    float4 v = *reinterpret_cast<const float4*>(&src[i]);
    *reinterpret_cast<uint2*>(&dst[i]) = make_uint2(pkh(v.x, v.y), pkh(v.z, v.w));
}

// ---------------------------------------------------------------------------
// GEMM via mma.sync fp16: C[M,N] = A[M,K=1024] @ B[K,N] + bias
// CTA 128x128, 4 warps (2x2), warp tile 64x64, BK=64, 3-stage cp.async,
// SW128 rows, 2 CTAs/SM.
// KIND 0: QKV scatter (ldB=3072). KIND 1: f32 out.
// ---------------------------------------------------------------------------
#define GM_AMAT 16384                  // 128 rows * 128B
#define GM_BHALF 8192                  // 64 k-rows * 128B (one 64-col n-half)
#define GM_STG (GM_AMAT + 2 * GM_BHALF)   // 32768
#define GEMM_SMEM (3 * GM_STG)         // 98304

#define QSCALE 0.1803368801111f        // 0.125 * log2(e)

template <int KIND>
__global__ __launch_bounds__(128, 2)
void mma_gemm(const fp16* __restrict__ amat, const fp16* __restrict__ bmat,
              const float* __restrict__ bias, float* __restrict__ out) {
    extern __shared__ char smem[];
    const uint32_t sb = smem_u32(smem);
    const int tid = threadIdx.x;
    const int lane = tid & 31;
    const int wid = tid >> 5;          // 0..3
    const int wm = wid & 1;            // row half (64 rows)
    const int wn = wid >> 1;           // col half (64 cols)
    const int n0 = blockIdx.x * 128;
    const int m0 = blockIdx.y * 128;
    const int NCH = 16;                // K=1024 / 64
    const int ldB = (KIND == 0) ? 3072 : 1024;

    auto load_chunk = [&](int ch) {
        const uint32_t base = sb + (ch % 3) * GM_STG;
        const int k0 = ch * 64;
        #pragma unroll
        for (int i = 0; i < 8; i++) {
            const int idx = tid + i * 128;     // 0..1023
            const int r = idx >> 3;            // 0..127
            const int c = idx & 7;
            cp16(base + SWZ128(r * 128 + c * 16),
                 amat + (size_t)(m0 + r) * 1024 + k0 + c * 8);
        }
        #pragma unroll
        for (int i = 0; i < 8; i++) {
            const int idx = tid + i * 128;     // 0..1023
            const int r = idx >> 4;            // 0..63 (k row)
            const int c = idx & 15;
            const uint32_t half = (c >> 3);
            const uint32_t cw = c & 7;
            cp16(base + GM_AMAT + half * GM_BHALF + SWZ128(r * 128 + cw * 16),
                 bmat + (size_t)(k0 + r) * ldB + n0 + c * 8);
        }
        CP_COMMIT();
    };

    float acc[4][8][4] = {};
    load_chunk(0);
    load_chunk(1);

    for (int ch = 0; ch < NCH; ch++) {
        __syncthreads();               // stage (ch+2)%3 free
        if (ch + 2 < NCH)      { load_chunk(ch + 2); cp_wait<2>(); }
        else if (ch + 1 < NCH) { cp_wait<1>(); }
        else                   { cp_wait<0>(); }
        __syncthreads();               // chunk ch visible

        const uint32_t base = sb + (ch % 3) * GM_STG;
        const uint32_t bbase = base + GM_AMAT + wn * GM_BHALF;
        #pragma unroll
        for (int ks = 0; ks < 4; ks++) {
            const int cc = ks * 2 + (lane >> 4);
            uint32_t ah[4][4];
            #pragma unroll
            for (int mt = 0; mt < 4; mt++) {
                const int row = wm * 64 + mt * 16 + (lane & 15);
                ldsm_x4(ah[mt], base + SWZ128(row * 128 + cc * 16));
            }
            #pragma unroll
            for (int bp = 0; bp < 4; bp++) {
                uint32_t bh[4];
                ldsm_x4_t(bh, bbase +
                    SWZ128((ks * 16 + (lane & 15)) * 128 +
                           (bp * 2 + (lane >> 4)) * 16));
                #pragma unroll
                for (int mt = 0; mt < 4; mt++) {
                    mma_fp16(acc[mt][2 * bp + 0], ah[mt], bh[0], bh[1]);
                    mma_fp16(acc[mt][2 * bp + 1], ah[mt], bh[2], bh[3]);
                }
            }
        }
    }
    __syncthreads();   // mainloop smem reads done before epilogue overwrite

    // Epilogue: stage fp32 C in smem, then coalesced writes.
    float* sC = reinterpret_cast<float*>(smem);   // [128][132]
    #pragma unroll
    for (int mt = 0; mt < 4; mt++)
        #pragma unroll
        for (int nt = 0; nt < 8; nt++) {
            const int r = wm * 64 + mt * 16 + (lane >> 2);
            const int c = wn * 64 + nt * 8 + 2 * (lane & 3);
            sC[r * 132 + c]           = acc[mt][nt][0];
            sC[r * 132 + c + 1]       = acc[mt][nt][1];
            sC[(r + 8) * 132 + c]     = acc[mt][nt][2];
            sC[(r + 8) * 132 + c + 1] = acc[mt][nt][3];
        }
    __syncthreads();

    #pragma unroll
    for (int it = 0; it < 32; it++) {
        const int idx = tid + it * 128;     // 0..4095
        const int r = idx >> 5;
        const int c4 = (idx & 31) * 4;
        float4 v = *reinterpret_cast<float4*>(&sC[r * 132 + c4]);
        const float4 bb = *reinterpret_cast<const float4*>(&bias[n0 + c4]);
        v.x += bb.x; v.y += bb.y; v.z += bb.z; v.w += bb.w;
        const int m = m0 + r;
        if (KIND == 0) {
            const int n = n0 + c4;
            const int slot = n >> 10;
            const int h = (n >> 6) & 15;
            const int d = n & 63;
            const int b = m >> 11;
            const int t = m & 2047;
            const size_t o = ((size_t)(b * NHEAD + h) * TSEQ + t) * HDIM + d;
            fp16* dst;
            if (slot == 0) {
                v.x *= QSCALE; v.y *= QSCALE; v.z *= QSCALE; v.w *= QSCALE;
                dst = g_q16;
            } else if (slot == 1) dst = g_k16;
            else                  dst = g_v16;
            *reinterpret_cast<uint2*>(&dst[o]) =
                make_uint2(pkh(v.x, v.y), pkh(v.z, v.w));
        } else {
            *reinterpret_cast<float4*>(&out[(size_t)m * 1024 + n0 + c4]) = v;
        }
    }
}

// ---------------------------------------------------------------------------
// Flash attention. CTA: 4 warps x 64 q-rows = 256 q-rows (halves KV traffic),
// 128-key steps, two 64-key sub-tiles, two sequential 32-row groups per warp.
// QK^T: Q16 @ K16 (1-product). P@V: Ph @ V16.
// Softmax: packed fp16 exp2; row sums via ones-column MMA.
// ---------------------------------------------------------------------------
#define AQ_MAT 32768                      // 256 q-rows x 128B (swizzled)
#define AKV_BLK 16384                     // 128 keys x 128B
#define AKV_STG (2 * AKV_BLK)             // K + V (128 keys each)
#define ATTN_SMEM (AQ_MAT + 2 * AKV_STG)  // 98304

__global__ __launch_bounds__(128, 2)
void attn_kernel() {
    extern __shared__ char smem[];
    const uint32_t sb = smem_u32(smem);
    const int tid = threadIdx.x;
    const int lane = tid & 31;
    const int w = tid >> 5;            // 0..3
    const int qt = blockIdx.x;         // 0..7 (256-row tiles)
    const int h  = blockIdx.y;
    const int b  = blockIdx.z;

    const size_t head_off = (size_t)(b * NHEAD + h) * TSEQ * HDIM;
    const size_t q_off = head_off + (size_t)qt * 256 * HDIM;

    auto load_kv = [&](int step) {       // 128 keys per step
        const uint32_t base = sb + AQ_MAT + (step & 1) * AKV_STG;
        #pragma unroll
        for (int i = 0; i < 8; i++) {
            const int idx = tid + i * 128;     // 0..1023
            const int r = idx >> 3;            // 0..127
            const int c = idx & 7;
            const uint32_t off = SWZ128(r * 128 + c * 16);
            const size_t g = head_off + (size_t)(step * 128 + r) * HDIM + c * 8;
            cp16(base + off, g_k16 + g);
            cp16(base + AKV_BLK + off, g_v16 + g);
        }
        CP_COMMIT();
    };

    // Q tile (256 rows) rides with KV(0) in one group.
    #pragma unroll
    for (int i = 0; i < 16; i++) {
        const int idx = tid + i * 128;     // 0..2047
        const int r = idx >> 3;
        const int c = idx & 7;
        cp16(sb + SWZ128(r * 128 + c * 16), g_q16 + q_off + (size_t)r * HDIM + c * 8);
    }
    load_kv(0);

    float o[4][8][4] = {};             // 4 row-tiles of 16
    float csum[4][4] = {};
    float mr[4][2] = { {-1e30f,-1e30f},{-1e30f,-1e30f},
                       {-1e30f,-1e30f},{-1e30f,-1e30f} };

    for (int step = 0; step < 16; step++) {
        __syncthreads();               // other stage free
        if (step + 1 < 16) { load_kv(step + 1); cp_wait<1>(); }
        else               { cp_wait<0>(); }
        __syncthreads();               // step data visible

        const uint32_t kvK = sb + AQ_MAT + (step & 1) * AKV_STG;
        const uint32_t kvV = kvK + AKV_BLK;

        #pragma unroll
        for (int sub = 0; sub < 2; sub++) {
            const uint32_t kRow0 = sub * 64;

            #pragma unroll
            for (int g = 0; g < 2; g++) {      // 32-row groups
                // ---- S = Q @ K^T (1-product) ----
                float s[2][8][4] = {};
                #pragma unroll
                for (int ks = 0; ks < 4; ks++) {
                    const int cc = ks * 2 + (lane >> 4);
                    uint32_t aq[2][4];
                    #pragma unroll
                    for (int mt = 0; mt < 2; mt++) {
                        const int row = w * 64 + g * 32 + mt * 16 + (lane & 15);
                        ldsm_x4(aq[mt], sb + SWZ128(row * 128 + cc * 16));
                    }
                    #pragma unroll
                    for (int bp = 0; bp < 4; bp++) {
                        uint32_t kh[4];
                        ldsm_x4(kh, kvK +
                            SWZ128((kRow0 + bp * 16 + (lane & 15)) * 128 + cc * 16));
                        #pragma unroll
                        for (int mt = 0; mt < 2; mt++) {
                            mma_fp16(s[mt][2 * bp + 0], aq[mt], kh[0], kh[2]);
                            mma_fp16(s[mt][2 * bp + 1], aq[mt], kh[1], kh[3]);
                        }
                    }
                }

                // ---- Online softmax per row-half ----
                float mn[2][2], al[2][2];
                #pragma unroll
                for (int mt = 0; mt < 2; mt++) {
                    const int m = g * 2 + mt;
                    float tm0 = -1e30f, tm1 = -1e30f;
                    #pragma unroll
                    for (int nt = 0; nt < 8; nt++) {
                        tm0 = fmaxf(tm0, fmaxf(s[mt][nt][0], s[mt][nt][1]));
                        tm1 = fmaxf(tm1, fmaxf(s[mt][nt][2], s[mt][nt][3]));
                    }
                    tm0 = fmaxf(tm0, __shfl_xor_sync(0xffffffffu, tm0, 1));
                    tm0 = fmaxf(tm0, __shfl_xor_sync(0xffffffffu, tm0, 2));
                    tm1 = fmaxf(tm1, __shfl_xor_sync(0xffffffffu, tm1, 1));
                    tm1 = fmaxf(tm1, __shfl_xor_sync(0xffffffffu, tm1, 2));
                    mn[mt][0] = fmaxf(mr[m][0], tm0);
                    mn[mt][1] = fmaxf(mr[m][1], tm1);
                    al[mt][0] = ex2(mr[m][0] - mn[mt][0]);
                    al[mt][1] = ex2(mr[m][1] - mn[mt][1]);
                    mr[m][0] = mn[mt][0];
                    mr[m][1] = mn[mt][1];
                    #pragma unroll
                    for (int nt = 0; nt < 8; nt++) {
                        o[m][nt][0] *= al[mt][0]; o[m][nt][1] *= al[mt][0];
                        o[m][nt][2] *= al[mt][1]; o[m][nt][3] *= al[mt][1];
                    }
                    csum[m][0] *= al[mt][0]; csum[m][1] *= al[mt][0];
                    csum[m][2] *= al[mt][1]; csum[m][3] *= al[mt][1];
                }

                // ---- fp16 exp2 + P @ V + ones-MMA row sums ----
                #pragma unroll
                for (int j = 0; j < 4; j++) {
                    uint32_t vh[4][4];
                    #pragma unroll
                    for (int dp = 0; dp < 4; dp++) {
                        ldsm_x4_t(vh[dp], kvV +
                            SWZ128((kRow0 + j * 16 + (lane & 15)) * 128 +
                                   (dp * 2 + (lane >> 4)) * 16));
                    }
                    #pragma unroll
                    for (int mt = 0; mt < 2; mt++) {
                        const int m = g * 2 + mt;
                        uint32_t aPh[4];
                        #pragma unroll
                        for (int t = 0; t < 2; t++) {
                            const int nt = 2 * j + t;
                            aPh[2 * t] = ex2h2(pkh(s[mt][nt][0] - mn[mt][0],
                                                   s[mt][nt][1] - mn[mt][0]));
                            aPh[2 * t + 1] = ex2h2(pkh(s[mt][nt][2] - mn[mt][1],
                                                       s[mt][nt][3] - mn[mt][1]));
                        }
                        mma_fp16(csum[m], aPh, ONES_H2, ONES_H2);
                        #pragma unroll
                        for (int dp = 0; dp < 4; dp++) {
                            mma_fp16(o[m][2 * dp + 0], aPh, vh[dp][0], vh[dp][1]);
                            mma_fp16(o[m][2 * dp + 1], aPh, vh[dp][2], vh[dp][3]);
                        }
                    }
                }
            }
        }
    }

    // ---- Normalize + write single fp16 to g_at [B,T,C] ----
    #pragma unroll
    for (int m = 0; m < 4; m++) {
        const float inv0 = 1.0f / csum[m][0];
        const float inv1 = 1.0f / csum[m][2];
        const int row0 = qt * 256 + w * 64 + m * 16 + (lane >> 2);
        #pragma unroll
        for (int nt = 0; nt < 8; nt++) {
            const int col = h * HDIM + nt * 8 + 2 * (lane & 3);
            const size_t o0 = ((size_t)b * TSEQ + row0) * CDIM + col;
            const size_t o1 = ((size_t)b * TSEQ + row0 + 8) * CDIM + col;
            *reinterpret_cast<uint32_t*>(&g_at[o0]) =
                pkh(o[m][nt][0] * inv0, o[m][nt][1] * inv0);
            *reinterpret_cast<uint32_t*>(&g_at[o1]) =
                pkh(o[m][nt][2] * inv1, o[m][nt][3] * inv1);
        }
    }
}

// ---------------------------------------------------------------------------
// Launch
// ---------------------------------------------------------------------------
extern "C" void kernel_launch(void* const* d_in, const int* in_sizes, int n_in,
                              void* d_out, int out_size) {
    (void)in_sizes; (void)n_in; (void)out_size;
    const float* x      = (const float*)d_in[0];
    const float* w_qkv  = (const float*)d_in[1];
    const float* b_qkv  = (const float*)d_in[2];
    const float* w_proj = (const float*)d_in[3];
    const float* b_proj = (const float*)d_in[4];
    float* out = (float*)d_out;

    cudaFuncSetAttribute(mma_gemm<0>, cudaFuncAttributeMaxDynamicSharedMemorySize, GEMM_SMEM);
    cudaFuncSetAttribute(mma_gemm<1>, cudaFuncAttributeMaxDynamicSharedMemorySize, GEMM_SMEM);
    cudaFuncSetAttribute(attn_kernel, cudaFuncAttributeMaxDynamicSharedMemorySize, ATTN_SMEM);

    fp16 *x16, *wq, *wp, *at;
    cudaGetSymbolAddress((void**)&x16, g_x16);
    cudaGetSymbolAddress((void**)&wq,  g_wq);
    cudaGetSymbolAddress((void**)&wp,  g_wp);
    cudaGetSymbolAddress((void**)&at,  g_at);

    // One merged conversion launch (x, w_qkv, w_proj)
    convert_all_kernel<<<8192, 256>>>(x, x16, w_qkv, wq, w_proj, wp);

    // QKV GEMM: M=4096, N=3072 -> grid (24, 32)
    mma_gemm<0><<<dim3(24, 32), 128, GEMM_SMEM>>>(x16, wq, b_qkv, nullptr);

    // Attention: (8 q-tiles of 256 rows, 16 heads, 2 batch) = 256 CTAs
    attn_kernel<<<dim3(8, NHEAD, BATCH), 128, ATTN_SMEM>>>();

    // Projection: M=4096, N=1024 -> grid (8, 32)
    mma_gemm<1><<<dim3(8, 32), 128, GEMM_SMEM>>>(at, wp, b_proj, out);
}

// round 14
// speedup vs baseline: 1.4037x; 1.4037x over previous
#include <cuda_runtime.h>
#include <cuda_bf16.h>
#include <cuda_fp16.h>
#include <math.h>
#include <cstdint>

#define BATCH   2
#define TSEQ    2048
#define CDIM    1024
#define NHEAD   16
#define HDIM    64

typedef __half fp16;

// ---------------------------------------------------------------------------
// Scratch (__device__ globals; no allocation allowed)
// ---------------------------------------------------------------------------
#define QKV_ELEMS (BATCH * NHEAD * TSEQ * HDIM)
__device__ __align__(128) fp16 g_x16[4096 * 1024];    // x single fp16
__device__ __align__(128) fp16 g_wq[1024 * 3072];     // natural [K][N]
__device__ __align__(128) fp16 g_wp[1024 * 1024];     // natural [K][N]
__device__ __align__(128) fp16 g_q16[QKV_ELEMS];      // q scaled, single fp16
__device__ __align__(128) fp16 g_k16[QKV_ELEMS];      // k single fp16
__device__ __align__(128) fp16 g_v16[QKV_ELEMS];      // v single fp16
__device__ __align__(128) fp16 g_at[4096 * 1024];     // attention out, single

// ---------------------------------------------------------------------------
// Helpers
// ---------------------------------------------------------------------------
__device__ __forceinline__ uint32_t smem_u32(const void* p) {
    uint32_t a;
    asm("{ .reg .u64 t; cvta.to.shared.u64 t, %1; cvt.u32.u64 %0, t; }" : "=r"(a) : "l"(p));
    return a;
}

__device__ __forceinline__ void cp16(uint32_t dst, const void* src) {
    asm volatile("cp.async.cg.shared.global [%0], [%1], 16;" :: "r"(dst), "l"(src));
}
#define CP_COMMIT() asm volatile("cp.async.commit_group;" ::: "memory")
template <int N>
__device__ __forceinline__ void cp_wait() {
    asm volatile("cp.async.wait_group %0;" :: "n"(N) : "memory");
}

__device__ __forceinline__ void ldsm_x4(uint32_t* r, uint32_t addr) {
    asm volatile("ldmatrix.sync.aligned.m8n8.x4.shared.b16 {%0,%1,%2,%3}, [%4];"
                 : "=r"(r[0]), "=r"(r[1]), "=r"(r[2]), "=r"(r[3]) : "r"(addr));
}
__device__ __forceinline__ void ldsm_x4_t(uint32_t* r, uint32_t addr) {
    asm volatile("ldmatrix.sync.aligned.m8n8.x4.trans.shared.b16 {%0,%1,%2,%3}, [%4];"
                 : "=r"(r[0]), "=r"(r[1]), "=r"(r[2]), "=r"(r[3]) : "r"(addr));
}

// D += A * B, m16n8k16 fp16 -> f32
__device__ __forceinline__ void mma_fp16(float* c, const uint32_t* a,
                                         uint32_t b0, uint32_t b1) {
    asm volatile(
        "mma.sync.aligned.m16n8k16.row.col.f32.f16.f16.f32 "
        "{%0,%1,%2,%3}, {%4,%5,%6,%7}, {%8,%9}, {%0,%1,%2,%3};"
        : "+f"(c[0]), "+f"(c[1]), "+f"(c[2]), "+f"(c[3])
        : "r"(a[0]), "r"(a[1]), "r"(a[2]), "r"(a[3]), "r"(b0), "r"(b1));
}

// fp16 pack helpers
__device__ __forceinline__ uint32_t pkh(float a, float b) {
    __half2 h = __floats2half2_rn(a, b);
    return *reinterpret_cast<uint32_t*>(&h);
}

__device__ __forceinline__ float ex2(float x) {
    float y;
    asm("ex2.approx.ftz.f32 %0, %1;" : "=f"(y) : "f"(x));
    return y;
}
// packed fp16 exp2 (one MUFU for two elements)
__device__ __forceinline__ uint32_t ex2h2(uint32_t x) {
    uint32_t y;
    asm("ex2.approx.f16x2 %0, %1;" : "=r"(y) : "r"(x));
    return y;
}

#define ONES_H2 0x3C003C00u   // fp16 {1.0, 1.0}

// swizzle for 128B rows
#define SWZ128(off) ((uint32_t)(off) ^ ((((uint32_t)(off)) >> 3) & 0x70))

// ---------------------------------------------------------------------------
// Merged conversion kernel: three f32 -> fp16 conversions in one launch.
// Segments: x (4M elems), w_qkv (3M), w_proj (1M) -> 2M threads total.
// ---------------------------------------------------------------------------
__global__ __launch_bounds__(256)
void convert_all_kernel(const float* __restrict__ x, fp16* __restrict__ x16,
                        const float* __restrict__ wq, fp16* __restrict__ wq16,
                        const float* __restrict__ wp, fp16* __restrict__ wp16) {
    const int t = blockIdx.x * 256 + threadIdx.x;   // 0 .. 2M-1
    const float* src;
    fp16* dst;
    int i;
    if (t < 1048576)               { src = x;  dst = x16;  i = t * 4; }
    else if (t < 1048576 + 786432) { src = wq; dst = wq16; i = (t - 1048576) * 4; }
    else                           { src = wp; dst = wp16; i = (t - 1835008) * 4; }
    float4 v = *reinterpret_cast<const float4*>(&src[i]);
    *reinterpret_cast<uint2*>(&dst[i]) = make_uint2(pkh(v.x, v.y), pkh(v.z, v.w));
}

// ---------------------------------------------------------------------------
// GEMM via mma.sync fp16: C[M,N] = A[M,K=1024] @ B[K,N] + bias
// CTA 128x128, 4 warps (2x2), warp tile 64x64, BK=64, 3-stage cp.async,
// SW128 rows, 2 CTAs/SM.
// KIND 0: QKV scatter (ldB=3072). KIND 1: f32 out.
// ---------------------------------------------------------------------------
#define GM_AMAT 16384                  // 128 rows * 128B
#define GM_BHALF 8192                  // 64 k-rows * 128B (one 64-col n-half)
#define GM_STG (GM_AMAT + 2 * GM_BHALF)   // 32768
#define GEMM_SMEM (3 * GM_STG)         // 98304

#define QSCALE 0.1803368801111f        // 0.125 * log2(e)

template <int KIND>
__global__ __launch_bounds__(128, 2)
void mma_gemm(const fp16* __restrict__ amat, const fp16* __restrict__ bmat,
              const float* __restrict__ bias, float* __restrict__ out) {
    extern __shared__ char smem[];
    const uint32_t sb = smem_u32(smem);
    const int tid = threadIdx.x;
    const int lane = tid & 31;
    const int wid = tid >> 5;          // 0..3
    const int wm = wid & 1;            // row half (64 rows)
    const int wn = wid >> 1;           // col half (64 cols)
    const int n0 = blockIdx.x * 128;
    const int m0 = blockIdx.y * 128;
    const int NCH = 16;                // K=1024 / 64
    const int ldB = (KIND == 0) ? 3072 : 1024;

    auto load_chunk = [&](int ch) {
        const uint32_t base = sb + (ch % 3) * GM_STG;
        const int k0 = ch * 64;
        #pragma unroll
        for (int i = 0; i < 8; i++) {
            const int idx = tid + i * 128;     // 0..1023
            const int r = idx >> 3;            // 0..127
            const int c = idx & 7;
            cp16(base + SWZ128(r * 128 + c * 16),
                 amat + (size_t)(m0 + r) * 1024 + k0 + c * 8);
        }
        #pragma unroll
        for (int i = 0; i < 8; i++) {
            const int idx = tid + i * 128;     // 0..1023
            const int r = idx >> 4;            // 0..63 (k row)
            const int c = idx & 15;
            const uint32_t half = (c >> 3);
            const uint32_t cw = c & 7;
            cp16(base + GM_AMAT + half * GM_BHALF + SWZ128(r * 128 + cw * 16),
                 bmat + (size_t)(k0 + r) * ldB + n0 + c * 8);
        }
        CP_COMMIT();
    };

    float acc[4][8][4] = {};
    load_chunk(0);
    load_chunk(1);

    for (int ch = 0; ch < NCH; ch++) {
        __syncthreads();               // stage (ch+2)%3 free
        if (ch + 2 < NCH)      { load_chunk(ch + 2); cp_wait<2>(); }
        else if (ch + 1 < NCH) { cp_wait<1>(); }
        else                   { cp_wait<0>(); }
        __syncthreads();               // chunk ch visible

        const uint32_t base = sb + (ch % 3) * GM_STG;
        const uint32_t bbase = base + GM_AMAT + wn * GM_BHALF;
        #pragma unroll
        for (int ks = 0; ks < 4; ks++) {
            const int cc = ks * 2 + (lane >> 4);
            uint32_t ah[4][4];
            #pragma unroll
            for (int mt = 0; mt < 4; mt++) {
                const int row = wm * 64 + mt * 16 + (lane & 15);
                ldsm_x4(ah[mt], base + SWZ128(row * 128 + cc * 16));
            }
            #pragma unroll
            for (int bp = 0; bp < 4; bp++) {
                uint32_t bh[4];
                ldsm_x4_t(bh, bbase +
                    SWZ128((ks * 16 + (lane & 15)) * 128 +
                           (bp * 2 + (lane >> 4)) * 16));
                #pragma unroll
                for (int mt = 0; mt < 4; mt++) {
                    mma_fp16(acc[mt][2 * bp + 0], ah[mt], bh[0], bh[1]);
                    mma_fp16(acc[mt][2 * bp + 1], ah[mt], bh[2], bh[3]);
                }
            }
        }
    }
    __syncthreads();   // mainloop smem reads done before epilogue overwrite

    // Epilogue: stage fp32 C in smem, then coalesced writes.
    float* sC = reinterpret_cast<float*>(smem);   // [128][132]
    #pragma unroll
    for (int mt = 0; mt < 4; mt++)
        #pragma unroll
        for (int nt = 0; nt < 8; nt++) {
            const int r = wm * 64 + mt * 16 + (lane >> 2);
            const int c = wn * 64 + nt * 8 + 2 * (lane & 3);
            sC[r * 132 + c]           = acc[mt][nt][0];
            sC[r * 132 + c + 1]       = acc[mt][nt][1];
            sC[(r + 8) * 132 + c]     = acc[mt][nt][2];
            sC[(r + 8) * 132 + c + 1] = acc[mt][nt][3];
        }
    __syncthreads();

    #pragma unroll
    for (int it = 0; it < 32; it++) {
        const int idx = tid + it * 128;     // 0..4095
        const int r = idx >> 5;
        const int c4 = (idx & 31) * 4;
        float4 v = *reinterpret_cast<float4*>(&sC[r * 132 + c4]);
        const float4 bb = *reinterpret_cast<const float4*>(&bias[n0 + c4]);
        v.x += bb.x; v.y += bb.y; v.z += bb.z; v.w += bb.w;
        const int m = m0 + r;
        if (KIND == 0) {
            const int n = n0 + c4;
            const int slot = n >> 10;
            const int h = (n >> 6) & 15;
            const int d = n & 63;
            const int b = m >> 11;
            const int t = m & 2047;
            const size_t o = ((size_t)(b * NHEAD + h) * TSEQ + t) * HDIM + d;
            fp16* dst;
            if (slot == 0) {
                v.x *= QSCALE; v.y *= QSCALE; v.z *= QSCALE; v.w *= QSCALE;
                dst = g_q16;
            } else if (slot == 1) dst = g_k16;
            else                  dst = g_v16;
            *reinterpret_cast<uint2*>(&dst[o]) =
                make_uint2(pkh(v.x, v.y), pkh(v.z, v.w));
        } else {
            *reinterpret_cast<float4*>(&out[(size_t)m * 1024 + n0 + c4]) = v;
        }
    }
}

// ---------------------------------------------------------------------------
// Flash attention. CTA: 4 warps x 32 q-rows = 128 q-rows, 128-key steps.
// QK^T: Q16 @ K16 (1-product, 2 row-halves share K frags).
// P@V: Ph @ V16 (V frags shared across row-halves).
// Softmax: packed fp16 exp2; row sums via ones-column MMA.
// ---------------------------------------------------------------------------
#define AQ_MAT 16384                      // 128 q-rows x 128B (swizzled)
#define AKV_BLK 16384                     // 128 keys x 128B
#define AKV_STG (2 * AKV_BLK)             // K + V (128 keys each)
#define ATTN_SMEM (AQ_MAT + 2 * AKV_STG)  // 81920

__global__ __launch_bounds__(128, 2)
void attn_kernel() {
    extern __shared__ char smem[];
    const uint32_t sb = smem_u32(smem);
    const int tid = threadIdx.x;
    const int lane = tid & 31;
    const int w = tid >> 5;            // 0..3
    const int qt = blockIdx.x;         // 0..15 (128-row tiles)
    const int h  = blockIdx.y;
    const int b  = blockIdx.z;

    const size_t head_off = (size_t)(b * NHEAD + h) * TSEQ * HDIM;
    const size_t q_off = head_off + (size_t)qt * 128 * HDIM;

    auto load_kv = [&](int step) {       // 128 keys per step
        const uint32_t base = sb + AQ_MAT + (step & 1) * AKV_STG;
        #pragma unroll
        for (int i = 0; i < 8; i++) {
            const int idx = tid + i * 128;     // 0..1023
            const int r = idx >> 3;            // 0..127
            const int c = idx & 7;
            const uint32_t off = SWZ128(r * 128 + c * 16);
            const size_t g = head_off + (size_t)(step * 128 + r) * HDIM + c * 8;
            cp16(base + off, g_k16 + g);
            cp16(base + AKV_BLK + off, g_v16 + g);
        }
        CP_COMMIT();
    };

    // Q tile (128 rows) rides with KV(0) in one group.
    #pragma unroll
    for (int i = 0; i < 8; i++) {
        const int idx = tid + i * 128;     // 0..1023
        const int r = idx >> 3;
        const int c = idx & 7;
        cp16(sb + SWZ128(r * 128 + c * 16), g_q16 + q_off + (size_t)r * HDIM + c * 8);
    }
    load_kv(0);

    float o[2][8][4] = {};
    float csum[2][4] = {};
    float mr[2][2] = { {-1e30f, -1e30f}, {-1e30f, -1e30f} };

    for (int step = 0; step < 16; step++) {
        __syncthreads();               // other stage free
        if (step + 1 < 16) { load_kv(step + 1); cp_wait<1>(); }
        else               { cp_wait<0>(); }
        __syncthreads();               // step data visible

        const uint32_t kvK = sb + AQ_MAT + (step & 1) * AKV_STG;
        const uint32_t kvV = kvK + AKV_BLK;

        #pragma unroll
        for (int sub = 0; sub < 2; sub++) {
            const uint32_t kRow0 = sub * 64;

            // ---- S = Q @ K^T (1-product), two 16-row halves ----
            float s[2][8][4] = {};
            #pragma unroll
            for (int ks = 0; ks < 4; ks++) {
                const int cc = ks * 2 + (lane >> 4);
                uint32_t aq[2][4];
                #pragma unroll
                for (int mt = 0; mt < 2; mt++) {
                    const int row = w * 32 + mt * 16 + (lane & 15);
                    ldsm_x4(aq[mt], sb + SWZ128(row * 128 + cc * 16));
                }
                #pragma unroll
                for (int bp = 0; bp < 4; bp++) {
                    uint32_t kh[4];
                    const uint32_t koff =
                        SWZ128((kRow0 + bp * 16 + (lane & 15)) * 128 + cc * 16);
                    ldsm_x4(kh, kvK + koff);
                    #pragma unroll
                    for (int mt = 0; mt < 2; mt++) {
                        mma_fp16(s[mt][2 * bp + 0], aq[mt], kh[0], kh[2]);
                        mma_fp16(s[mt][2 * bp + 1], aq[mt], kh[1], kh[3]);
                    }
                }
            }

            // ---- Online softmax per row-half ----
            float mn[2][2], al[2][2];
            #pragma unroll
            for (int mt = 0; mt < 2; mt++) {
                float tm0 = -1e30f, tm1 = -1e30f;
                #pragma unroll
                for (int nt = 0; nt < 8; nt++) {
                    tm0 = fmaxf(tm0, fmaxf(s[mt][nt][0], s[mt][nt][1]));
                    tm1 = fmaxf(tm1, fmaxf(s[mt][nt][2], s[mt][nt][3]));
                }
                tm0 = fmaxf(tm0, __shfl_xor_sync(0xffffffffu, tm0, 1));
                tm0 = fmaxf(tm0, __shfl_xor_sync(0xffffffffu, tm0, 2));
                tm1 = fmaxf(tm1, __shfl_xor_sync(0xffffffffu, tm1, 1));
                tm1 = fmaxf(tm1, __shfl_xor_sync(0xffffffffu, tm1, 2));
                mn[mt][0] = fmaxf(mr[mt][0], tm0);
                mn[mt][1] = fmaxf(mr[mt][1], tm1);
                al[mt][0] = ex2(mr[mt][0] - mn[mt][0]);
                al[mt][1] = ex2(mr[mt][1] - mn[mt][1]);
                mr[mt][0] = mn[mt][0];
                mr[mt][1] = mn[mt][1];
                #pragma unroll
                for (int nt = 0; nt < 8; nt++) {
                    o[mt][nt][0] *= al[mt][0]; o[mt][nt][1] *= al[mt][0];
                    o[mt][nt][2] *= al[mt][1]; o[mt][nt][3] *= al[mt][1];
                }
                csum[mt][0] *= al[mt][0]; csum[mt][1] *= al[mt][0];
                csum[mt][2] *= al[mt][1]; csum[mt][3] *= al[mt][1];
            }

            // ---- fp16 exp2 + P @ V + ones-MMA row sums (V shared) ----
            #pragma unroll
            for (int j = 0; j < 4; j++) {
                uint32_t vh[4][4];
                #pragma unroll
                for (int dp = 0; dp < 4; dp++) {
                    const uint32_t voff =
                        SWZ128((kRow0 + j * 16 + (lane & 15)) * 128 +
                               (dp * 2 + (lane >> 4)) * 16);
                    ldsm_x4_t(vh[dp], kvV + voff);
                }
                #pragma unroll
                for (int mt = 0; mt < 2; mt++) {
                    uint32_t aPh[4];
                    #pragma unroll
                    for (int t = 0; t < 2; t++) {
                        const int nt = 2 * j + t;
                        aPh[2 * t] = ex2h2(pkh(s[mt][nt][0] - mn[mt][0],
                                               s[mt][nt][1] - mn[mt][0]));
                        aPh[2 * t + 1] = ex2h2(pkh(s[mt][nt][2] - mn[mt][1],
                                                   s[mt][nt][3] - mn[mt][1]));
                    }
                    mma_fp16(csum[mt], aPh, ONES_H2, ONES_H2);
                    #pragma unroll
                    for (int dp = 0; dp < 4; dp++) {
                        mma_fp16(o[mt][2 * dp + 0], aPh, vh[dp][0], vh[dp][1]);
                        mma_fp16(o[mt][2 * dp + 1], aPh, vh[dp][2], vh[dp][3]);
                    }
                }
            }
        }
    }

    // ---- Normalize + write single fp16 to g_at [B,T,C] ----
    #pragma unroll
    for (int mt = 0; mt < 2; mt++) {
        const float inv0 = 1.0f / csum[mt][0];
        const float inv1 = 1.0f / csum[mt][2];
        const int row0 = qt * 128 + w * 32 + mt * 16 + (lane >> 2);
        #pragma unroll
        for (int nt = 0; nt < 8; nt++) {
            const int col = h * HDIM + nt * 8 + 2 * (lane & 3);
            const size_t o0 = ((size_t)b * TSEQ + row0) * CDIM + col;
            const size_t o1 = ((size_t)b * TSEQ + row0 + 8) * CDIM + col;
            *reinterpret_cast<uint32_t*>(&g_at[o0]) =
                pkh(o[mt][nt][0] * inv0, o[mt][nt][1] * inv0);
            *reinterpret_cast<uint32_t*>(&g_at[o1]) =
                pkh(o[mt][nt][2] * inv1, o[mt][nt][3] * inv1);
        }
    }
}

// ---------------------------------------------------------------------------
// Launch
// ---------------------------------------------------------------------------
extern "C" void kernel_launch(void* const* d_in, const int* in_sizes, int n_in,
                              void* d_out, int out_size) {
    (void)in_sizes; (void)n_in; (void)out_size;
    const float* x      = (const float*)d_in[0];
    const float* w_qkv  = (const float*)d_in[1];
    const float* b_qkv  = (const float*)d_in[2];
    const float* w_proj = (const float*)d_in[3];
    const float* b_proj = (const float*)d_in[4];
    float* out = (float*)d_out;

    cudaFuncSetAttribute(mma_gemm<0>, cudaFuncAttributeMaxDynamicSharedMemorySize, GEMM_SMEM);
    cudaFuncSetAttribute(mma_gemm<1>, cudaFuncAttributeMaxDynamicSharedMemorySize, GEMM_SMEM);
    cudaFuncSetAttribute(attn_kernel, cudaFuncAttributeMaxDynamicSharedMemorySize, ATTN_SMEM);

    fp16 *x16, *wq, *wp, *at;
    cudaGetSymbolAddress((void**)&x16, g_x16);
    cudaGetSymbolAddress((void**)&wq,  g_wq);
    cudaGetSymbolAddress((void**)&wp,  g_wp);
    cudaGetSymbolAddress((void**)&at,  g_at);

    // One merged conversion launch (x, w_qkv, w_proj)
    convert_all_kernel<<<8192, 256>>>(x, x16, w_qkv, wq, w_proj, wp);

    // QKV GEMM: M=4096, N=3072 -> grid (24, 32)
    mma_gemm<0><<<dim3(24, 32), 128, GEMM_SMEM>>>(x16, wq, b_qkv, nullptr);

    // Attention: (16 q-tiles of 128 rows, 16 heads, 2 batch)
    attn_kernel<<<dim3(16, NHEAD, BATCH), 128, ATTN_SMEM>>>();

    // Projection: M=4096, N=1024 -> grid (8, 32)
    mma_gemm<1><<<dim3(8, 32), 128, GEMM_SMEM>>>(at, wp, b_proj, out);
}

// round 15
// speedup vs baseline: 1.4160x; 1.0088x over previous
#include <cuda_runtime.h>
#include <cuda_bf16.h>
#include <cuda_fp16.h>
#include <math.h>
#include <cstdint>

#define BATCH   2
#define TSEQ    2048
#define CDIM    1024
#define NHEAD   16
#define HDIM    64

typedef __half fp16;

// ---------------------------------------------------------------------------
// Scratch (__device__ globals; no allocation allowed)
// ---------------------------------------------------------------------------
#define QKV_ELEMS (BATCH * NHEAD * TSEQ * HDIM)
__device__ __align__(128) fp16 g_x16[4096 * 1024];    // x single fp16
__device__ __align__(128) fp16 g_wq[1024 * 3072];     // natural [K][N]
__device__ __align__(128) fp16 g_wp[1024 * 1024];     // natural [K][N]
__device__ __align__(128) fp16 g_q16[QKV_ELEMS];      // q scaled, single fp16
__device__ __align__(128) fp16 g_k16[QKV_ELEMS];      // k single fp16
__device__ __align__(128) fp16 g_v16[QKV_ELEMS];      // v single fp16
__device__ __align__(128) fp16 g_at[4096 * 1024];     // attention out, single

// ---------------------------------------------------------------------------
// Helpers
// ---------------------------------------------------------------------------
__device__ __forceinline__ uint32_t smem_u32(const void* p) {
    uint32_t a;
    asm("{ .reg .u64 t; cvta.to.shared.u64 t, %1; cvt.u32.u64 %0, t; }" : "=r"(a) : "l"(p));
    return a;
}

__device__ __forceinline__ void cp16(uint32_t dst, const void* src) {
    asm volatile("cp.async.cg.shared.global [%0], [%1], 16;" :: "r"(dst), "l"(src));
}
#define CP_COMMIT() asm volatile("cp.async.commit_group;" ::: "memory")
template <int N>
__device__ __forceinline__ void cp_wait() {
    asm volatile("cp.async.wait_group %0;" :: "n"(N) : "memory");
}

__device__ __forceinline__ void ldsm_x4(uint32_t* r, uint32_t addr) {
    asm volatile("ldmatrix.sync.aligned.m8n8.x4.shared.b16 {%0,%1,%2,%3}, [%4];"
                 : "=r"(r[0]), "=r"(r[1]), "=r"(r[2]), "=r"(r[3]) : "r"(addr));
}
__device__ __forceinline__ void ldsm_x4_t(uint32_t* r, uint32_t addr) {
    asm volatile("ldmatrix.sync.aligned.m8n8.x4.trans.shared.b16 {%0,%1,%2,%3}, [%4];"
                 : "=r"(r[0]), "=r"(r[1]), "=r"(r[2]), "=r"(r[3]) : "r"(addr));
}

// D += A * B, m16n8k16 fp16 -> f32
__device__ __forceinline__ void mma_fp16(float* c, const uint32_t* a,
                                         uint32_t b0, uint32_t b1) {
    asm volatile(
        "mma.sync.aligned.m16n8k16.row.col.f32.f16.f16.f32 "
        "{%0,%1,%2,%3}, {%4,%5,%6,%7}, {%8,%9}, {%0,%1,%2,%3};"
        : "+f"(c[0]), "+f"(c[1]), "+f"(c[2]), "+f"(c[3])
        : "r"(a[0]), "r"(a[1]), "r"(a[2]), "r"(a[3]), "r"(b0), "r"(b1));
}
// D += A * B, m16n8k16 fp16 -> fp16 (dual-rate; C packed f16x2 pairs)
__device__ __forceinline__ void mma_h16(uint32_t* c, const uint32_t* a,
                                        uint32_t b0, uint32_t b1) {
    asm volatile(
        "mma.sync.aligned.m16n8k16.row.col.f16.f16.f16.f16 "
        "{%0,%1}, {%2,%3,%4,%5}, {%6,%7}, {%0,%1};"
        : "+r"(c[0]), "+r"(c[1])
        : "r"(a[0]), "r"(a[1]), "r"(a[2]), "r"(a[3]), "r"(b0), "r"(b1));
}

// fp16 pack helpers
__device__ __forceinline__ uint32_t pkh(float a, float b) {
    __half2 h = __floats2half2_rn(a, b);
    return *reinterpret_cast<uint32_t*>(&h);
}
__device__ __forceinline__ float h_el0(uint32_t v) {
    return __half2float(__ushort_as_half((unsigned short)(v & 0xffffu)));
}
__device__ __forceinline__ float h_el1(uint32_t v) {
    return __half2float(__ushort_as_half((unsigned short)(v >> 16)));
}
__device__ __forceinline__ uint32_t hsub2u(uint32_t a, uint32_t b) {
    __half2 r = __hsub2(*reinterpret_cast<__half2*>(&a),
                        *reinterpret_cast<__half2*>(&b));
    return *reinterpret_cast<uint32_t*>(&r);
}
__device__ __forceinline__ uint32_t hmax2u(uint32_t a, uint32_t b) {
    __half2 r = __hmax2(*reinterpret_cast<__half2*>(&a),
                        *reinterpret_cast<__half2*>(&b));
    return *reinterpret_cast<uint32_t*>(&r);
}

__device__ __forceinline__ float ex2(float x) {
    float y;
    asm("ex2.approx.ftz.f32 %0, %1;" : "=f"(y) : "f"(x));
    return y;
}
// packed fp16 exp2 (one MUFU for two elements)
__device__ __forceinline__ uint32_t ex2h2(uint32_t x) {
    uint32_t y;
    asm("ex2.approx.f16x2 %0, %1;" : "=r"(y) : "r"(x));
    return y;
}

#define ONES_H2  0x3C003C00u   // fp16 {1.0, 1.0}
#define NINF_H2  0xFC00FC00u   // fp16 {-inf, -inf}

// swizzle for 128B rows
#define SWZ128(off) ((uint32_t)(off) ^ ((((uint32_t)(off)) >> 3) & 0x70))

// ---------------------------------------------------------------------------
// Merged conversion kernel: three f32 -> fp16 conversions in one launch.
// ---------------------------------------------------------------------------
__global__ __launch_bounds__(256)
void convert_all_kernel(const float* __restrict__ x, fp16* __restrict__ x16,
                        const float* __restrict__ wq, fp16* __restrict__ wq16,
                        const float* __restrict__ wp, fp16* __restrict__ wp16) {
    const int t = blockIdx.x * 256 + threadIdx.x;   // 0 .. 2M-1
    const float* src;
    fp16* dst;
    int i;
    if (t < 1048576)               { src = x;  dst = x16;  i = t * 4; }
    else if (t < 1048576 + 786432) { src = wq; dst = wq16; i = (t - 1048576) * 4; }
    else                           { src = wp; dst = wp16; i = (t - 1835008) * 4; }
    float4 v = *reinterpret_cast<const float4*>(&src[i]);
    *reinterpret_cast<uint2*>(&dst[i]) = make_uint2(pkh(v.x, v.y), pkh(v.z, v.w));
}

// ---------------------------------------------------------------------------
// GEMM via mma.sync fp16: C[M,N] = A[M,K=1024] @ B[K,N] + bias
// CTA 128x128, 4 warps (2x2), warp tile 64x64, BK=64, 3-stage cp.async,
// SW128 rows, 2 CTAs/SM.
// KIND 0: QKV scatter (ldB=3072). KIND 1: f32 out.
// ---------------------------------------------------------------------------
#define GM_AMAT 16384                  // 128 rows * 128B
#define GM_BHALF 8192                  // 64 k-rows * 128B (one 64-col n-half)
#define GM_STG (GM_AMAT + 2 * GM_BHALF)   // 32768
#define GEMM_SMEM (3 * GM_STG)         // 98304

#define QSCALE 0.1803368801111f        // 0.125 * log2(e)

template <int KIND>
__global__ __launch_bounds__(128, 2)
void mma_gemm(const fp16* __restrict__ amat, const fp16* __restrict__ bmat,
              const float* __restrict__ bias, float* __restrict__ out) {
    extern __shared__ char smem[];
    const uint32_t sb = smem_u32(smem);
    const int tid = threadIdx.x;
    const int lane = tid & 31;
    const int wid = tid >> 5;          // 0..3
    const int wm = wid & 1;            // row half (64 rows)
    const int wn = wid >> 1;           // col half (64 cols)
    const int n0 = blockIdx.x * 128;
    const int m0 = blockIdx.y * 128;
    const int NCH = 16;                // K=1024 / 64
    const int ldB = (KIND == 0) ? 3072 : 1024;

    auto load_chunk = [&](int ch) {
        const uint32_t base = sb + (ch % 3) * GM_STG;
        const int k0 = ch * 64;
        #pragma unroll
        for (int i = 0; i < 8; i++) {
            const int idx = tid + i * 128;     // 0..1023
            const int r = idx >> 3;            // 0..127
            const int c = idx & 7;
            cp16(base + SWZ128(r * 128 + c * 16),
                 amat + (size_t)(m0 + r) * 1024 + k0 + c * 8);
        }
        #pragma unroll
        for (int i = 0; i < 8; i++) {
            const int idx = tid + i * 128;     // 0..1023
            const int r = idx >> 4;            // 0..63 (k row)
            const int c = idx & 15;
            const uint32_t half = (c >> 3);
            const uint32_t cw = c & 7;
            cp16(base + GM_AMAT + half * GM_BHALF + SWZ128(r * 128 + cw * 16),
                 bmat + (size_t)(k0 + r) * ldB + n0 + c * 8);
        }
        CP_COMMIT();
    };

    float acc[4][8][4] = {};
    load_chunk(0);
    load_chunk(1);

    for (int ch = 0; ch < NCH; ch++) {
        __syncthreads();               // stage (ch+2)%3 free
        if (ch + 2 < NCH)      { load_chunk(ch + 2); cp_wait<2>(); }
        else if (ch + 1 < NCH) { cp_wait<1>(); }
        else                   { cp_wait<0>(); }
        __syncthreads();               // chunk ch visible

        const uint32_t base = sb + (ch % 3) * GM_STG;
        const uint32_t bbase = base + GM_AMAT + wn * GM_BHALF;
        #pragma unroll
        for (int ks = 0; ks < 4; ks++) {
            const int cc = ks * 2 + (lane >> 4);
            uint32_t ah[4][4];
            #pragma unroll
            for (int mt = 0; mt < 4; mt++) {
                const int row = wm * 64 + mt * 16 + (lane & 15);
                ldsm_x4(ah[mt], base + SWZ128(row * 128 + cc * 16));
            }
            #pragma unroll
            for (int bp = 0; bp < 4; bp++) {
                uint32_t bh[4];
                ldsm_x4_t(bh, bbase +
                    SWZ128((ks * 16 + (lane & 15)) * 128 +
                           (bp * 2 + (lane >> 4)) * 16));
                #pragma unroll
                for (int mt = 0; mt < 4; mt++) {
                    mma_fp16(acc[mt][2 * bp + 0], ah[mt], bh[0], bh[1]);
                    mma_fp16(acc[mt][2 * bp + 1], ah[mt], bh[2], bh[3]);
                }
            }
        }
    }
    __syncthreads();   // mainloop smem reads done before epilogue overwrite

    // Epilogue: stage fp32 C in smem, then coalesced writes.
    float* sC = reinterpret_cast<float*>(smem);   // [128][132]
    #pragma unroll
    for (int mt = 0; mt < 4; mt++)
        #pragma unroll
        for (int nt = 0; nt < 8; nt++) {
            const int r = wm * 64 + mt * 16 + (lane >> 2);
            const int c = wn * 64 + nt * 8 + 2 * (lane & 3);
            sC[r * 132 + c]           = acc[mt][nt][0];
            sC[r * 132 + c + 1]       = acc[mt][nt][1];
            sC[(r + 8) * 132 + c]     = acc[mt][nt][2];
            sC[(r + 8) * 132 + c + 1] = acc[mt][nt][3];
        }
    __syncthreads();

    #pragma unroll
    for (int it = 0; it < 32; it++) {
        const int idx = tid + it * 128;     // 0..4095
        const int r = idx >> 5;
        const int c4 = (idx & 31) * 4;
        float4 v = *reinterpret_cast<float4*>(&sC[r * 132 + c4]);
        const float4 bb = *reinterpret_cast<const float4*>(&bias[n0 + c4]);
        v.x += bb.x; v.y += bb.y; v.z += bb.z; v.w += bb.w;
        const int m = m0 + r;
        if (KIND == 0) {
            const int n = n0 + c4;
            const int slot = n >> 10;
            const int h = (n >> 6) & 15;
            const int d = n & 63;
            const int b = m >> 11;
            const int t = m & 2047;
            const size_t o = ((size_t)(b * NHEAD + h) * TSEQ + t) * HDIM + d;
            fp16* dst;
            if (slot == 0) {
                v.x *= QSCALE; v.y *= QSCALE; v.z *= QSCALE; v.w *= QSCALE;
                dst = g_q16;
            } else if (slot == 1) dst = g_k16;
            else                  dst = g_v16;
            *reinterpret_cast<uint2*>(&dst[o]) =
                make_uint2(pkh(v.x, v.y), pkh(v.z, v.w));
        } else {
            *reinterpret_cast<float4*>(&out[(size_t)m * 1024 + n0 + c4]) = v;
        }
    }
}

// ---------------------------------------------------------------------------
// Flash attention. CTA: 4 warps x 32 q-rows = 128 q-rows, 128-key steps.
// QK^T: Q16 @ K16 with FP16 ACCUMULATOR (dual-rate HMMA); scores stay packed
// f16x2, flowing straight into ex2.f16x2 and the PV A-fragments (no packs).
// P@V: Ph @ V16, f32 accum. Softmax row sums via ones-column MMA (f32).
// ---------------------------------------------------------------------------
#define AQ_MAT 16384                      // 128 q-rows x 128B (swizzled)
#define AKV_BLK 16384                     // 128 keys x 128B
#define AKV_STG (2 * AKV_BLK)             // K + V (128 keys each)
#define ATTN_SMEM (AQ_MAT + 2 * AKV_STG)  // 81920

__global__ __launch_bounds__(128, 2)
void attn_kernel() {
    extern __shared__ char smem[];
    const uint32_t sb = smem_u32(smem);
    const int tid = threadIdx.x;
    const int lane = tid & 31;
    const int w = tid >> 5;            // 0..3
    const int qt = blockIdx.x;         // 0..15 (128-row tiles)
    const int h  = blockIdx.y;
    const int b  = blockIdx.z;

    const size_t head_off = (size_t)(b * NHEAD + h) * TSEQ * HDIM;
    const size_t q_off = head_off + (size_t)qt * 128 * HDIM;

    auto load_kv = [&](int step) {       // 128 keys per step
        const uint32_t base = sb + AQ_MAT + (step & 1) * AKV_STG;
        #pragma unroll
        for (int i = 0; i < 8; i++) {
            const int idx = tid + i * 128;     // 0..1023
            const int r = idx >> 3;            // 0..127
            const int c = idx & 7;
            const uint32_t off = SWZ128(r * 128 + c * 16);
            const size_t g = head_off + (size_t)(step * 128 + r) * HDIM + c * 8;
            cp16(base + off, g_k16 + g);
            cp16(base + AKV_BLK + off, g_v16 + g);
        }
        CP_COMMIT();
    };

    // Q tile (128 rows) rides with KV(0) in one group.
    #pragma unroll
    for (int i = 0; i < 8; i++) {
        const int idx = tid + i * 128;     // 0..1023
        const int r = idx >> 3;
        const int c = idx & 7;
        cp16(sb + SWZ128(r * 128 + c * 16), g_q16 + q_off + (size_t)r * HDIM + c * 8);
    }
    load_kv(0);

    float o[2][8][4] = {};
    float csum[2][4] = {};
    float mr[2][2] = { {-1e30f, -1e30f}, {-1e30f, -1e30f} };

    for (int step = 0; step < 16; step++) {
        __syncthreads();               // other stage free
        if (step + 1 < 16) { load_kv(step + 1); cp_wait<1>(); }
        else               { cp_wait<0>(); }
        __syncthreads();               // step data visible

        const uint32_t kvK = sb + AQ_MAT + (step & 1) * AKV_STG;
        const uint32_t kvV = kvK + AKV_BLK;

        #pragma unroll
        for (int sub = 0; sub < 2; sub++) {
            const uint32_t kRow0 = sub * 64;

            // ---- S = Q @ K^T (f16 accum, dual rate), two 16-row halves ----
            // s16[mt][nt][0] = packed (row-group 0, cols 2λ,2λ+1)
            // s16[mt][nt][1] = packed (row-group +8, same cols)
            uint32_t s16[2][8][2] = {};
            #pragma unroll
            for (int ks = 0; ks < 4; ks++) {
                const int cc = ks * 2 + (lane >> 4);
                uint32_t aq[2][4];
                #pragma unroll
                for (int mt = 0; mt < 2; mt++) {
                    const int row = w * 32 + mt * 16 + (lane & 15);
                    ldsm_x4(aq[mt], sb + SWZ128(row * 128 + cc * 16));
                }
                #pragma unroll
                for (int bp = 0; bp < 4; bp++) {
                    uint32_t kh[4];
                    const uint32_t koff =
                        SWZ128((kRow0 + bp * 16 + (lane & 15)) * 128 + cc * 16);
                    ldsm_x4(kh, kvK + koff);
                    #pragma unroll
                    for (int mt = 0; mt < 2; mt++) {
                        mma_h16(s16[mt][2 * bp + 0], aq[mt], kh[0], kh[2]);
                        mma_h16(s16[mt][2 * bp + 1], aq[mt], kh[1], kh[3]);
                    }
                }
            }

            // ---- Online softmax per row-half (packed max reduce) ----
            float mn[2][2], al[2][2];
            uint32_t mn2[2][2];
            #pragma unroll
            for (int mt = 0; mt < 2; mt++) {
                uint32_t tp0 = NINF_H2, tp1 = NINF_H2;
                #pragma unroll
                for (int nt = 0; nt < 8; nt++) {
                    tp0 = hmax2u(tp0, s16[mt][nt][0]);
                    tp1 = hmax2u(tp1, s16[mt][nt][1]);
                }
                float tm0 = fmaxf(h_el0(tp0), h_el1(tp0));
                float tm1 = fmaxf(h_el0(tp1), h_el1(tp1));
                tm0 = fmaxf(tm0, __shfl_xor_sync(0xffffffffu, tm0, 1));
                tm0 = fmaxf(tm0, __shfl_xor_sync(0xffffffffu, tm0, 2));
                tm1 = fmaxf(tm1, __shfl_xor_sync(0xffffffffu, tm1, 1));
                tm1 = fmaxf(tm1, __shfl_xor_sync(0xffffffffu, tm1, 2));
                mn[mt][0] = fmaxf(mr[mt][0], tm0);
                mn[mt][1] = fmaxf(mr[mt][1], tm1);
                al[mt][0] = ex2(mr[mt][0] - mn[mt][0]);
                al[mt][1] = ex2(mr[mt][1] - mn[mt][1]);
                mr[mt][0] = mn[mt][0];
                mr[mt][1] = mn[mt][1];
                mn2[mt][0] = pkh(mn[mt][0], mn[mt][0]);
                mn2[mt][1] = pkh(mn[mt][1], mn[mt][1]);
                #pragma unroll
                for (int nt = 0; nt < 8; nt++) {
                    o[mt][nt][0] *= al[mt][0]; o[mt][nt][1] *= al[mt][0];
                    o[mt][nt][2] *= al[mt][1]; o[mt][nt][3] *= al[mt][1];
                }
                csum[mt][0] *= al[mt][0]; csum[mt][1] *= al[mt][0];
                csum[mt][2] *= al[mt][1]; csum[mt][3] *= al[mt][1];
            }

            // ---- fp16 exp2 directly on packed scores + P @ V ----
            #pragma unroll
            for (int j = 0; j < 4; j++) {
                uint32_t vh[4][4];
                #pragma unroll
                for (int dp = 0; dp < 4; dp++) {
                    const uint32_t voff =
                        SWZ128((kRow0 + j * 16 + (lane & 15)) * 128 +
                               (dp * 2 + (lane >> 4)) * 16);
                    ldsm_x4_t(vh[dp], kvV + voff);
                }
                #pragma unroll
                for (int mt = 0; mt < 2; mt++) {
                    uint32_t aPh[4];
                    #pragma unroll
                    for (int t = 0; t < 2; t++) {
                        const int nt = 2 * j + t;
                        aPh[2 * t]     = ex2h2(hsub2u(s16[mt][nt][0], mn2[mt][0]));
                        aPh[2 * t + 1] = ex2h2(hsub2u(s16[mt][nt][1], mn2[mt][1]));
                    }
                    mma_fp16(csum[mt], aPh, ONES_H2, ONES_H2);
                    #pragma unroll
                    for (int dp = 0; dp < 4; dp++) {
                        mma_fp16(o[mt][2 * dp + 0], aPh, vh[dp][0], vh[dp][1]);
                        mma_fp16(o[mt][2 * dp + 1], aPh, vh[dp][2], vh[dp][3]);
                    }
                }
            }
        }
    }

    // ---- Normalize + write single fp16 to g_at [B,T,C] ----
    #pragma unroll
    for (int mt = 0; mt < 2; mt++) {
        const float inv0 = 1.0f / csum[mt][0];
        const float inv1 = 1.0f / csum[mt][2];
        const int row0 = qt * 128 + w * 32 + mt * 16 + (lane >> 2);
        #pragma unroll
        for (int nt = 0; nt < 8; nt++) {
            const int col = h * HDIM + nt * 8 + 2 * (lane & 3);
            const size_t o0 = ((size_t)b * TSEQ + row0) * CDIM + col;
            const size_t o1 = ((size_t)b * TSEQ + row0 + 8) * CDIM + col;
            *reinterpret_cast<uint32_t*>(&g_at[o0]) =
                pkh(o[mt][nt][0] * inv0, o[mt][nt][1] * inv0);
            *reinterpret_cast<uint32_t*>(&g_at[o1]) =
                pkh(o[mt][nt][2] * inv1, o[mt][nt][3] * inv1);
        }
    }
}

// ---------------------------------------------------------------------------
// Launch
// ---------------------------------------------------------------------------
extern "C" void kernel_launch(void* const* d_in, const int* in_sizes, int n_in,
                              void* d_out, int out_size) {
    (void)in_sizes; (void)n_in; (void)out_size;
    const float* x      = (const float*)d_in[0];
    const float* w_qkv  = (const float*)d_in[1];
    const float* b_qkv  = (const float*)d_in[2];
    const float* w_proj = (const float*)d_in[3];
    const float* b_proj = (const float*)d_in[4];
    float* out = (float*)d_out;

    cudaFuncSetAttribute(mma_gemm<0>, cudaFuncAttributeMaxDynamicSharedMemorySize, GEMM_SMEM);
    cudaFuncSetAttribute(mma_gemm<1>, cudaFuncAttributeMaxDynamicSharedMemorySize, GEMM_SMEM);
    cudaFuncSetAttribute(attn_kernel, cudaFuncAttributeMaxDynamicSharedMemorySize, ATTN_SMEM);

    fp16 *x16, *wq, *wp, *at;
    cudaGetSymbolAddress((void**)&x16, g_x16);
    cudaGetSymbolAddress((void**)&wq,  g_wq);
    cudaGetSymbolAddress((void**)&wp,  g_wp);
    cudaGetSymbolAddress((void**)&at,  g_at);

    // One merged conversion launch (x, w_qkv, w_proj)
    convert_all_kernel<<<8192, 256>>>(x, x16, w_qkv, wq, w_proj, wp);

    // QKV GEMM: M=4096, N=3072 -> grid (24, 32)
    mma_gemm<0><<<dim3(24, 32), 128, GEMM_SMEM>>>(x16, wq, b_qkv, nullptr);

    // Attention: (16 q-tiles of 128 rows, 16 heads, 2 batch)
    attn_kernel<<<dim3(16, NHEAD, BATCH), 128, ATTN_SMEM>>>();

    // Projection: M=4096, N=1024 -> grid (8, 32)
    mma_gemm<1><<<dim3(8, 32), 128, GEMM_SMEM>>>(at, wp, b_proj, out);
}